// round 1
// baseline (speedup 1.0000x reference)
#include <cuda_runtime.h>
#include <math.h>

#define BB 2
#define LL 1024
#define HH 8
#define DD 64
#define SS 10
#define T2 20   // 2S
#define RR 128
#define TL 32   // l-tile per block

// small precomputed tables (no allocation allowed -> __device__ globals)
__device__ float g_tpfr[HH*DD*SS];   // 2*pi*sigmoid(freqs)/2
__device__ float g_co[HH*DD*SS];     // cos(offsets)
__device__ float g_so[HH*DD*SS];     // sin(offsets)
__device__ float g_coef[HH*DD*T2];   // softplus(gains)[t%S] * 1/sqrt(R*D)

__global__ void spe_precompute(const float* __restrict__ freqs,
                               const float* __restrict__ offsets,
                               const float* __restrict__ gains) {
    int i = blockIdx.x * blockDim.x + threadIdx.x;
    const float scale = rsqrtf((float)(RR * DD));
    if (i < HH*DD*SS) {
        float f = freqs[i];
        float fr = 0.5f / (1.0f + expf(-f));          // sigmoid/2 (exact /2)
        g_tpfr[i] = 6.28318530717958647692f * fr;     // two_pi * fr (f32)
        float o = offsets[i];
        float so, co;
        sincosf(o, &so, &co);
        g_co[i] = co;
        g_so[i] = so;
    }
    if (i < HH*DD*T2) {
        int hd = i / T2;
        int t  = i - hd * T2;
        float x = gains[hd*SS + (t % SS)];
        // stable softplus = max(x,0) + log1p(exp(-|x|))
        float sp = fmaxf(x, 0.0f) + log1pf(expf(-fabsf(x)));
        g_coef[i] = sp * scale;
    }
}

__global__ __launch_bounds__(256, 2)
void spe_main(const float* __restrict__ qg,
              const float* __restrict__ kg,
              const float* __restrict__ zg,
              float* __restrict__ out) {
    __shared__ __align__(16) float qtile[TL][DD];
    __shared__ __align__(16) float ktile[TL][DD];
    __shared__ __align__(16) float zsm[T2][RR];
    __shared__ float aqs[TL][T2];
    __shared__ float aks[TL][T2];

    const int l0  = blockIdx.x * TL;
    const int h   = blockIdx.y;
    const int b   = blockIdx.z;
    const int tid = threadIdx.x;
    const int tx  = tid & 31;   // 32 r-groups of 4
    const int ty  = tid >> 5;   // 8 l-groups of 4

    // load q/k tiles: [TL][DD], rows contiguous in global (d innermost)
    for (int i = tid; i < TL*DD; i += 256) {
        int l = i >> 6;          // /DD
        int d = i & (DD-1);
        size_t gi = (((size_t)b*LL + (l0 + l))*HH + h)*DD + d;
        qtile[l][d] = qg[gi];
        ktile[l][d] = kg[gi];
    }

    float accq[4][4];
    float acck[4][4];
    #pragma unroll
    for (int j = 0; j < 4; ++j)
        #pragma unroll
        for (int r = 0; r < 4; ++r) { accq[j][r] = 0.0f; acck[j][r] = 0.0f; }

    const float* zb = zg + ((size_t)b*HH + h) * (size_t)DD * T2 * RR;

    for (int d = 0; d < DD; ++d) {
        __syncthreads();  // protect previous iteration's smem reads

        // stage z tile scaled by coef: zsm[t][r]
        {
            const float* zd = zb + (size_t)d * T2 * RR;
            const float* cf = g_coef + (h*DD + d) * T2;
            #pragma unroll
            for (int i = tid; i < T2*RR; i += 256) {
                zsm[0][0 + 0] = zsm[0][0]; // no-op to keep compiler quiet
                int t = i >> 7;            // /RR
                int r = i & (RR-1);
                zsm[t][r] = zd[i] * cf[t];
            }
        }

        // stage a rows: aq[l][t] = omega_q(h,d,l,t)*q, ak similarly
        {
            const int base = (h*DD + d) * SS;
            for (int p = tid; p < TL*SS; p += 256) {
                int l = p / SS;
                int s = p - l*SS;
                float tp = g_tpfr[base + s];
                float ph = tp * (float)(l0 + l);     // two_pi*fr*idx (f32)
                float sp, cp;
                sincosf(ph, &sp, &cp);
                float co = g_co[base + s];
                float so = g_so[base + s];
                float cq = cp*co - sp*so;            // cos(ph + off)
                float sq = sp*co + cp*so;            // sin(ph + off)
                float qv = qtile[l][d];
                float kv = ktile[l][d];
                aqs[l][2*s]   = cq * qv;
                aqs[l][2*s+1] = sq * qv;
                aks[l][2*s]   = cp * kv;
                aks[l][2*s+1] = sp * kv;
            }
        }
        __syncthreads();

        // accumulate: acc[l][r] += a[l][t] * zsm[t][r]
        #pragma unroll
        for (int t = 0; t < T2; ++t) {
            float4 zv = *(const float4*)&zsm[t][tx*4];
            #pragma unroll
            for (int j = 0; j < 4; ++j) {
                int l = ty*4 + j;
                float aq = aqs[l][t];
                float ak = aks[l][t];
                accq[j][0] += aq * zv.x;
                accq[j][1] += aq * zv.y;
                accq[j][2] += aq * zv.z;
                accq[j][3] += aq * zv.w;
                acck[j][0] += ak * zv.x;
                acck[j][1] += ak * zv.y;
                acck[j][2] += ak * zv.z;
                acck[j][3] += ak * zv.w;
            }
        }
    }

    // write qhat then khat (concatenated in d_out)
    const size_t khat_off = (size_t)BB * LL * HH * RR;
    #pragma unroll
    for (int j = 0; j < 4; ++j) {
        int l = l0 + ty*4 + j;
        size_t oi = (((size_t)b*LL + l)*HH + h)*RR + tx*4;
        float4 vq = make_float4(accq[j][0], accq[j][1], accq[j][2], accq[j][3]);
        float4 vk = make_float4(acck[j][0], acck[j][1], acck[j][2], acck[j][3]);
        *(float4*)&out[oi]            = vq;
        *(float4*)&out[khat_off + oi] = vk;
    }
}

extern "C" void kernel_launch(void* const* d_in, const int* in_sizes, int n_in,
                              void* d_out, int out_size) {
    const float* queries = (const float*)d_in[0];
    const float* keys    = (const float*)d_in[1];
    const float* freqs   = (const float*)d_in[2];
    const float* offsets = (const float*)d_in[3];
    const float* gains   = (const float*)d_in[4];
    const float* z       = (const float*)d_in[5];
    float* out = (float*)d_out;

    // precompute small tables
    int nPre = HH*DD*T2;  // 10240 covers both table sizes
    spe_precompute<<<(nPre + 255)/256, 256>>>(freqs, offsets, gains);

    dim3 grid(LL/TL, HH, BB);
    spe_main<<<grid, 256>>>(queries, keys, z, out);
}

// round 2
// speedup vs baseline: 1.1204x; 1.1204x over previous
#include <cuda_runtime.h>
#include <math.h>

#define BB 2
#define LL 1024
#define HH 8
#define DD 64
#define SS 10
#define T2 20   // 2S
#define RR 128
#define TL 32   // l-tile per block

typedef unsigned long long u64;

__device__ __forceinline__ u64 pack2(float lo, float hi) {
    u64 r; asm("mov.b64 %0, {%1, %2};" : "=l"(r) : "f"(lo), "f"(hi)); return r;
}
__device__ __forceinline__ void fma2(u64& d, u64 a, u64 b) {
    asm("fma.rn.f32x2 %0, %1, %2, %3;" : "=l"(d) : "l"(a), "l"(b), "l"(d));
}
__device__ __forceinline__ float2 unpack2(u64 v) {
    float2 f; asm("mov.b64 {%0, %1}, %2;" : "=f"(f.x), "=f"(f.y) : "l"(v)); return f;
}

// small precomputed tables (no allocation allowed -> __device__ globals)
__device__ float g_tpfr[HH*DD*SS];   // 2*pi*sigmoid(freqs)/2
__device__ float g_co[HH*DD*SS];     // cos(offsets)
__device__ float g_so[HH*DD*SS];     // sin(offsets)
__device__ float g_coef[HH*DD*T2];   // softplus(gains)[t%S] * 1/sqrt(R*D)

__global__ void spe_precompute(const float* __restrict__ freqs,
                               const float* __restrict__ offsets,
                               const float* __restrict__ gains) {
    int i = blockIdx.x * blockDim.x + threadIdx.x;
    const float scale = rsqrtf((float)(RR * DD));
    if (i < HH*DD*SS) {
        float f = freqs[i];
        float fr = 0.5f / (1.0f + expf(-f));          // sigmoid/2
        g_tpfr[i] = 6.28318530717958647692f * fr;     // two_pi * fr
        float o = offsets[i];
        float so, co;
        sincosf(o, &so, &co);
        g_co[i] = co;
        g_so[i] = so;
    }
    if (i < HH*DD*T2) {
        int hd = i / T2;
        int t  = i - hd * T2;
        float x = gains[hd*SS + (t % SS)];
        float sp = fmaxf(x, 0.0f) + log1pf(expf(-fabsf(x)));  // stable softplus
        g_coef[i] = sp * scale;
    }
}

__global__ __launch_bounds__(256, 2)
void spe_main(const float* __restrict__ qg,
              const float* __restrict__ kg,
              const float* __restrict__ zg,
              float* __restrict__ out) {
    __shared__ __align__(16) float zsm[2][T2][RR];       // 20480 B
    __shared__ __align__(16) float aqs[2][T2][TL];       //  5120 B
    __shared__ __align__(16) float aks[2][T2][TL];       //  5120 B
    __shared__ float qtile[TL][DD+1];                    //  8320 B (padded vs bank conflicts)
    __shared__ float ktile[TL][DD+1];                    //  8320 B

    const int l0  = blockIdx.x * TL;
    const int h   = blockIdx.y;
    const int b   = blockIdx.z;
    const int tid = threadIdx.x;
    const int tx  = tid & 31;   // 32 r-groups of 4
    const int ty  = tid >> 5;   // 8 l-groups of 4

    // load q/k tiles: [TL][DD+1], rows contiguous in global (d innermost)
    for (int i = tid; i < TL*DD; i += 256) {
        int l = i >> 6;          // /DD
        int d = i & (DD-1);
        size_t gi = (((size_t)b*LL + (l0 + l))*HH + h)*DD + d;
        qtile[l][d] = qg[gi];
        ktile[l][d] = kg[gi];
    }

    const float* zb = zg + ((size_t)b*HH + h) * (size_t)DD * T2 * RR;

    // staging: z tile (coef-scaled) into zsm[buf], a rows (transposed [t][l]) into aqs/aks[buf]
    auto stage = [&](int d, int buf) {
        const float4* zd4 = (const float4*)(zb + (size_t)d * T2 * RR);
        const float*  cf  = g_coef + (h*DD + d) * T2;
        for (int i = tid; i < T2*RR/4; i += 256) {
            int t = i >> 5;          // 32 float4 per t-row
            int c = i & 31;
            float4 v = zd4[i];
            float s = cf[t];
            v.x *= s; v.y *= s; v.z *= s; v.w *= s;
            *(float4*)&zsm[buf][t][c*4] = v;
        }
        const int base = (h*DD + d) * SS;
        for (int p = tid; p < TL*SS; p += 256) {
            int l = p & 31;          // l fastest -> conflict-free STS
            int s = p >> 5;
            float ph = g_tpfr[base + s] * (float)(l0 + l);
            float sp, cp;
            sincosf(ph, &sp, &cp);
            float co = g_co[base + s];
            float so = g_so[base + s];
            float qv = qtile[l][d];
            float kv = ktile[l][d];
            aqs[buf][2*s  ][l] = (cp*co - sp*so) * qv;   // cos(ph+off)*q
            aqs[buf][2*s+1][l] = (sp*co + cp*so) * qv;   // sin(ph+off)*q
            aks[buf][2*s  ][l] = cp * kv;
            aks[buf][2*s+1][l] = sp * kv;
        }
    };

    // accumulators: packed over l-pairs; [lpair][r], lanes = (l, l+1)
    u64 accq[2][4], acck[2][4];
    #pragma unroll
    for (int lp = 0; lp < 2; ++lp)
        #pragma unroll
        for (int r = 0; r < 4; ++r) { accq[lp][r] = 0ull; acck[lp][r] = 0ull; }

    __syncthreads();          // qtile/ktile ready
    stage(0, 0);
    __syncthreads();

    for (int d = 0; d < DD; ++d) {
        const int buf = d & 1;
        if (d + 1 < DD) stage(d + 1, buf ^ 1);

        #pragma unroll
        for (int t = 0; t < T2; ++t) {
            u64 aq0 = *(const u64*)&aqs[buf][t][ty*4];      // lanes l=4ty,4ty+1 (broadcast across warp)
            u64 aq1 = *(const u64*)&aqs[buf][t][ty*4 + 2];
            u64 ak0 = *(const u64*)&aks[buf][t][ty*4];
            u64 ak1 = *(const u64*)&aks[buf][t][ty*4 + 2];
            float4 zv = *(const float4*)&zsm[buf][t][tx*4]; // conflict-free
            u64 z0 = pack2(zv.x, zv.x);
            u64 z1 = pack2(zv.y, zv.y);
            u64 z2 = pack2(zv.z, zv.z);
            u64 z3 = pack2(zv.w, zv.w);
            fma2(accq[0][0], aq0, z0); fma2(accq[0][1], aq0, z1);
            fma2(accq[0][2], aq0, z2); fma2(accq[0][3], aq0, z3);
            fma2(accq[1][0], aq1, z0); fma2(accq[1][1], aq1, z1);
            fma2(accq[1][2], aq1, z2); fma2(accq[1][3], aq1, z3);
            fma2(acck[0][0], ak0, z0); fma2(acck[0][1], ak0, z1);
            fma2(acck[0][2], ak0, z2); fma2(acck[0][3], ak0, z3);
            fma2(acck[1][0], ak1, z0); fma2(acck[1][1], ak1, z1);
            fma2(acck[1][2], ak1, z2); fma2(acck[1][3], ak1, z3);
        }
        __syncthreads();      // stage(d+1) done; compute(d) done before buf reuse
    }

    // write qhat then khat (concatenated in d_out)
    const size_t khat_off = (size_t)BB * LL * HH * RR;
    #pragma unroll
    for (int lp = 0; lp < 2; ++lp) {
        float2 q0 = unpack2(accq[lp][0]);
        float2 q1 = unpack2(accq[lp][1]);
        float2 q2 = unpack2(accq[lp][2]);
        float2 q3 = unpack2(accq[lp][3]);
        float2 k0 = unpack2(acck[lp][0]);
        float2 k1 = unpack2(acck[lp][1]);
        float2 k2 = unpack2(acck[lp][2]);
        float2 k3 = unpack2(acck[lp][3]);
        int lA = l0 + ty*4 + 2*lp;
        size_t oA = (((size_t)b*LL + lA)*HH + h)*RR + tx*4;
        size_t oB = oA + (size_t)HH*RR;   // l+1
        *(float4*)&out[oA] = make_float4(q0.x, q1.x, q2.x, q3.x);
        *(float4*)&out[oB] = make_float4(q0.y, q1.y, q2.y, q3.y);
        *(float4*)&out[khat_off + oA] = make_float4(k0.x, k1.x, k2.x, k3.x);
        *(float4*)&out[khat_off + oB] = make_float4(k0.y, k1.y, k2.y, k3.y);
    }
}

extern "C" void kernel_launch(void* const* d_in, const int* in_sizes, int n_in,
                              void* d_out, int out_size) {
    const float* queries = (const float*)d_in[0];
    const float* keys    = (const float*)d_in[1];
    const float* freqs   = (const float*)d_in[2];
    const float* offsets = (const float*)d_in[3];
    const float* gains   = (const float*)d_in[4];
    const float* z       = (const float*)d_in[5];
    float* out = (float*)d_out;

    int nPre = HH*DD*T2;  // 10240 covers both table sizes
    spe_precompute<<<(nPre + 255)/256, 256>>>(freqs, offsets, gains);

    dim3 grid(LL/TL, HH, BB);
    spe_main<<<grid, 256>>>(queries, keys, z, out);
}

// round 4
// speedup vs baseline: 2.0714x; 1.8488x over previous
#include <cuda_runtime.h>
#include <cuda_bf16.h>
#include <math.h>
#include <stdint.h>

#define BB 2
#define LL 1024
#define HH 8
#define DD 64
#define SS 10
#define T2 20      // 2S
#define RR 128
#define KTOT 1280  // DD*T2
#define KC 64      // K per chunk
#define NCH 20     // KTOT/KC
#define MT 128     // M tile (l)

#define TSZ 16384          // one 128x64 bf16 tile (128B rows, swizzled)
#define BUFSZ (6*TSZ)      // Aqhi Aqlo Akhi Aklo Bhi Blo
#define SMEM_BYTES (2*BUFSZ + 1024)

static __device__ __align__(16) __nv_bfloat16 g_zThi[(size_t)BB*HH*RR*KTOT];
static __device__ __align__(16) __nv_bfloat16 g_zTlo[(size_t)BB*HH*RR*KTOT];

__device__ float g_tpfr[HH*DD*SS];   // 2*pi*sigmoid(freqs)/2
__device__ float g_co[HH*DD*SS];     // cos(offsets)
__device__ float g_so[HH*DD*SS];     // sin(offsets)
__device__ float g_coef[HH*DD*T2];   // softplus(gains)[t%S] / sqrt(R*D)

// ---------------- helpers ----------------
__device__ __forceinline__ uint32_t smem_u32(const void* p) {
    uint32_t a;
    asm("{ .reg .u64 t; cvta.to.shared.u64 t, %1; cvt.u32.u64 %0, t; }" : "=r"(a) : "l"(p));
    return a;
}
__device__ __forceinline__ uint32_t swz(uint32_t b) { return b ^ ((b >> 3) & 0x70); }
__device__ __forceinline__ uint32_t bf2(float x, float y) {
    __nv_bfloat162 h = __floats2bfloat162_rn(x, y);
    return *(uint32_t*)&h;
}
__device__ __forceinline__ void ldsm4(uint32_t* r, uint32_t a) {
    asm volatile("ldmatrix.sync.aligned.m8n8.x4.shared.b16 {%0,%1,%2,%3}, [%4];"
        : "=r"(r[0]), "=r"(r[1]), "=r"(r[2]), "=r"(r[3]) : "r"(a));
}
__device__ __forceinline__ void mma16816(float* d, const uint32_t* a, const uint32_t* b) {
    asm volatile(
        "mma.sync.aligned.m16n8k16.row.col.f32.bf16.bf16.f32 "
        "{%0,%1,%2,%3}, {%4,%5,%6,%7}, {%8,%9}, {%0,%1,%2,%3};"
        : "+f"(d[0]), "+f"(d[1]), "+f"(d[2]), "+f"(d[3])
        : "r"(a[0]), "r"(a[1]), "r"(a[2]), "r"(a[3]), "r"(b[0]), "r"(b[1]));
}

// ---------------- precompute tables ----------------
__global__ void spe_precompute(const float* __restrict__ freqs,
                               const float* __restrict__ offsets,
                               const float* __restrict__ gains) {
    int i = blockIdx.x * blockDim.x + threadIdx.x;
    const float scale = rsqrtf((float)(RR * DD));
    if (i < HH*DD*SS) {
        float f = freqs[i];
        float fr = 0.5f / (1.0f + expf(-f));
        g_tpfr[i] = 6.28318530717958647692f * fr;
        float o = offsets[i];
        float so, co;
        sincosf(o, &so, &co);
        g_co[i] = co;
        g_so[i] = so;
    }
    if (i < HH*DD*T2) {
        int hd = i / T2;
        int t  = i - hd * T2;
        float x = gains[hd*SS + (t % SS)];
        float sp = fmaxf(x, 0.0f) + log1pf(expf(-fabsf(x)));
        g_coef[i] = sp * scale;
    }
}

// ---------------- z transpose + coef-scale + bf16 hi/lo split ----------------
// z[b][h][d][t][r] (fp32) -> zT{hi,lo}[b][h][r][d*20+t] (bf16)
__global__ void spe_transpose(const float* __restrict__ zg) {
    int d = blockIdx.x, h = blockIdx.y, b = blockIdx.z;
    __shared__ float sm[T2][RR + 1];
    const float* zd = zg + (((size_t)(b*HH + h)*DD + d)*T2)*RR;
    const float* cf = g_coef + (h*DD + d)*T2;
    for (int i = threadIdx.x; i < T2*RR; i += 256) {
        int t = i >> 7, r = i & 127;
        sm[t][r] = zd[i] * cf[t];
    }
    __syncthreads();
    int r  = threadIdx.x >> 1;
    int t0 = (threadIdx.x & 1) * 10;
    size_t ob = ((size_t)(b*HH + h)*RR + r)*KTOT + d*T2 + t0;
    #pragma unroll
    for (int i = 0; i < 10; ++i) {
        float v = sm[t0 + i][r];
        __nv_bfloat16 hi = __float2bfloat16(v);
        __nv_bfloat16 lo = __float2bfloat16(v - __bfloat162float(hi));
        g_zThi[ob + i] = hi;
        g_zTlo[ob + i] = lo;
    }
}

// ---------------- main HMMA kernel ----------------
__global__ __launch_bounds__(512, 1)
void spe_mma_main(const float* __restrict__ qg,
                  const float* __restrict__ kg,
                  float* __restrict__ out) {
    extern __shared__ char smraw[];
    const uint32_t sb   = smem_u32(smraw);
    const uint32_t tb_u = (sb + 1023) & ~1023u;
    char* tb = smraw + (tb_u - sb);

    const int tid  = threadIdx.x;
    const int wid  = tid >> 5;
    const int lane = tid & 31;
    const int l0   = blockIdx.x * MT;
    const int h    = blockIdx.y;
    const int b    = blockIdx.z;

    const int mi = wid & 3;   // m32 block
    const int ni = wid >> 2;  // n32 block

    const __nv_bfloat16* zThi = g_zThi + (size_t)(b*HH + h)*RR*KTOT;
    const __nv_bfloat16* zTlo = g_zTlo + (size_t)(b*HH + h)*RR*KTOT;

    // stage chunk ch into buffer buf
    auto stage = [&](int ch, int buf) {
        char* tile = tb + buf*BUFSZ;
        const int k0 = ch * KC;
        // B: zT hi/lo, [128 r][64 k] bf16, 16B vector copies
        {
            char* tBh = tile + 4*TSZ;
            char* tBl = tile + 5*TSZ;
            #pragma unroll
            for (int u = 0; u < 2; ++u) {
                int idx = tid + u*512;         // 1024 units of 8 bf16
                int r   = idx >> 3;
                int kl8 = (idx & 7) * 8;
                uint32_t byte = swz((uint32_t)(r*128 + kl8*2));
                *(uint4*)(tBh + byte) = *(const uint4*)(zThi + (size_t)r*KTOT + k0 + kl8);
                *(uint4*)(tBl + byte) = *(const uint4*)(zTlo + (size_t)r*KTOT + k0 + kl8);
            }
        }
        // A: omega*q/k, bf16 hi/lo, [128 l][64 k]
        {
            char* tAqh = tile;
            char* tAql = tile + TSZ;
            char* tAkh = tile + 2*TSZ;
            char* tAkl = tile + 3*TSZ;
            #pragma unroll
            for (int u = 0; u < 8; ++u) {
                int unit = tid + u*512;        // 4096 units: (l, k-pair)
                int l  = unit >> 5;
                int pi = unit & 31;
                int k  = k0 + 2*pi;
                int d  = k / T2;
                int s  = (k - d*T2) >> 1;
                int gb = (h*DD + d)*SS + s;
                float ph = g_tpfr[gb] * (float)(l0 + l);
                float sp, cp;
                sincosf(ph, &sp, &cp);
                float co = g_co[gb], so = g_so[gb];
                float cq = cp*co - sp*so;
                float sq = sp*co + cp*so;
                size_t gi = (((size_t)b*LL + (l0 + l))*HH + h)*DD + d;
                float qv = __ldg(qg + gi);
                float kv = __ldg(kg + gi);
                float aqc = cq*qv, aqs = sq*qv, akc = cp*kv, aks = sp*kv;

                uint32_t byte = swz((uint32_t)(l*128 + pi*4));
                uint32_t qh = bf2(aqc, aqs);
                uint32_t kh = bf2(akc, aks);
                __nv_bfloat162 qh2 = *(__nv_bfloat162*)&qh;
                __nv_bfloat162 kh2 = *(__nv_bfloat162*)&kh;
                uint32_t ql = bf2(aqc - __bfloat162float(qh2.x), aqs - __bfloat162float(qh2.y));
                uint32_t kl = bf2(akc - __bfloat162float(kh2.x), aks - __bfloat162float(kh2.y));
                *(uint32_t*)(tAqh + byte) = qh;
                *(uint32_t*)(tAql + byte) = ql;
                *(uint32_t*)(tAkh + byte) = kh;
                *(uint32_t*)(tAkl + byte) = kl;
            }
        }
    };

    // accumulators: [msub 2][ntile 4][4]
    float accq[2][4][4];
    float acck[2][4][4];
    #pragma unroll
    for (int i = 0; i < 2; ++i)
        #pragma unroll
        for (int j = 0; j < 4; ++j)
            #pragma unroll
            for (int c = 0; c < 4; ++c) { accq[i][j][c] = 0.0f; acck[i][j][c] = 0.0f; }

    const uint32_t lanerow = lane & 15;
    const uint32_t lanecol = (uint32_t)(lane >> 4) * 16;

    stage(0, 0);
    __syncthreads();

    #pragma unroll 1
    for (int ch = 0; ch < NCH; ++ch) {
        const int buf = ch & 1;
        if (ch + 1 < NCH) stage(ch + 1, buf ^ 1);

        const uint32_t base = tb_u + buf*BUFSZ;
        #pragma unroll
        for (int kk = 0; kk < 4; ++kk) {
            const uint32_t kb = kk * 32;   // 16 elems * 2B
            // --- B fragments (shared by q and k) ---
            uint32_t bh[4][2], bl[4][2];
            {
                uint32_t t0[4], t1[4];
                uint32_t o0 = swz((ni*32 +  0 + lanerow)*128 + lanecol + kb);
                uint32_t o1 = swz((ni*32 + 16 + lanerow)*128 + lanecol + kb);
                ldsm4(t0, base + 4*TSZ + o0);
                ldsm4(t1, base + 4*TSZ + o1);
                bh[0][0]=t0[0]; bh[0][1]=t0[2]; bh[1][0]=t0[1]; bh[1][1]=t0[3];
                bh[2][0]=t1[0]; bh[2][1]=t1[2]; bh[3][0]=t1[1]; bh[3][1]=t1[3];
                ldsm4(t0, base + 5*TSZ + o0);
                ldsm4(t1, base + 5*TSZ + o1);
                bl[0][0]=t0[0]; bl[0][1]=t0[2]; bl[1][0]=t0[1]; bl[1][1]=t0[3];
                bl[2][0]=t1[0]; bl[2][1]=t1[2]; bl[3][0]=t1[1]; bl[3][1]=t1[3];
            }
            const uint32_t a0 = swz((mi*32 +  0 + lanerow)*128 + lanecol + kb);
            const uint32_t a1 = swz((mi*32 + 16 + lanerow)*128 + lanecol + kb);
            // --- q ---
            {
                uint32_t ah[2][4], al[2][4];
                ldsm4(ah[0], base + a0);
                ldsm4(ah[1], base + a1);
                ldsm4(al[0], base + TSZ + a0);
                ldsm4(al[1], base + TSZ + a1);
                #pragma unroll
                for (int s = 0; s < 2; ++s)
                    #pragma unroll
                    for (int j = 0; j < 4; ++j) {
                        mma16816(accq[s][j], ah[s], bh[j]);
                        mma16816(accq[s][j], al[s], bh[j]);
                        mma16816(accq[s][j], ah[s], bl[j]);
                    }
            }
            // --- k ---
            {
                uint32_t ah[2][4], al[2][4];
                ldsm4(ah[0], base + 2*TSZ + a0);
                ldsm4(ah[1], base + 2*TSZ + a1);
                ldsm4(al[0], base + 3*TSZ + a0);
                ldsm4(al[1], base + 3*TSZ + a1);
                #pragma unroll
                for (int s = 0; s < 2; ++s)
                    #pragma unroll
                    for (int j = 0; j < 4; ++j) {
                        mma16816(acck[s][j], ah[s], bh[j]);
                        mma16816(acck[s][j], al[s], bh[j]);
                        mma16816(acck[s][j], ah[s], bl[j]);
                    }
            }
        }
        __syncthreads();
    }

    // ---- epilogue: c-frag scatter ----
    const size_t khat_off = (size_t)BB * LL * HH * RR;
    #pragma unroll
    for (int s = 0; s < 2; ++s) {
        int row0 = l0 + mi*32 + s*16 + (lane >> 2);
        #pragma unroll
        for (int j = 0; j < 4; ++j) {
            int col = ni*32 + j*8 + (lane & 3)*2;
            size_t oA = (((size_t)b*LL + row0)*HH + h)*RR + col;
            size_t oB = oA + (size_t)8*HH*RR;   // row0 + 8
            *(float2*)(out + oA) = make_float2(accq[s][j][0], accq[s][j][1]);
            *(float2*)(out + oB) = make_float2(accq[s][j][2], accq[s][j][3]);
            *(float2*)(out + khat_off + oA) = make_float2(acck[s][j][0], acck[s][j][1]);
            *(float2*)(out + khat_off + oB) = make_float2(acck[s][j][2], acck[s][j][3]);
        }
    }
}

extern "C" void kernel_launch(void* const* d_in, const int* in_sizes, int n_in,
                              void* d_out, int out_size) {
    const float* queries = (const float*)d_in[0];
    const float* keys    = (const float*)d_in[1];
    const float* freqs   = (const float*)d_in[2];
    const float* offsets = (const float*)d_in[3];
    const float* gains   = (const float*)d_in[4];
    const float* z       = (const float*)d_in[5];
    float* out = (float*)d_out;

    cudaFuncSetAttribute(spe_mma_main, cudaFuncAttributeMaxDynamicSharedMemorySize, SMEM_BYTES);

    spe_precompute<<<(HH*DD*T2 + 255)/256, 256>>>(freqs, offsets, gains);
    spe_transpose<<<dim3(DD, HH, BB), 256>>>(z);
    spe_mma_main<<<dim3(LL/MT, HH, BB), 512, SMEM_BYTES>>>(queries, keys, out);
}

// round 5
// speedup vs baseline: 2.2306x; 1.0769x over previous
#include <cuda_runtime.h>
#include <cuda_bf16.h>
#include <math.h>
#include <stdint.h>

#define BB 2
#define LL 1024
#define HH 8
#define DD 64
#define SS 10
#define T2 20      // 2S
#define RR 128
#define KTOT 1280  // DD*T2
#define KC 64      // K per chunk
#define NCH 20     // KTOT/KC
#define MT 64      // M tile (l) per CTA

#define TSZA 8192            // 64x64 bf16 tile (128B rows, swizzled)
#define TSZB 16384           // 128x64 bf16 tile
#define OFF_BH (4*TSZA)
#define OFF_BL (4*TSZA + TSZB)
#define BUFSZ (4*TSZA + 2*TSZB)   // 64 KB: Aqhi Aqlo Akhi Aklo Bhi Blo
#define SMEM_BYTES (BUFSZ + 1024)

static __device__ __align__(16) __nv_bfloat16 g_zThi[(size_t)BB*HH*RR*KTOT];
static __device__ __align__(16) __nv_bfloat16 g_zTlo[(size_t)BB*HH*RR*KTOT];

__device__ float g_tpfr[HH*DD*SS];   // 2*pi*sigmoid(freqs)/2
__device__ float g_co[HH*DD*SS];     // cos(offsets)
__device__ float g_so[HH*DD*SS];     // sin(offsets)
__device__ float g_coef[HH*DD*T2];   // softplus(gains)[t%S] / sqrt(R*D)

// ---------------- helpers ----------------
__device__ __forceinline__ uint32_t smem_u32(const void* p) {
    uint32_t a;
    asm("{ .reg .u64 t; cvta.to.shared.u64 t, %1; cvt.u32.u64 %0, t; }" : "=r"(a) : "l"(p));
    return a;
}
__device__ __forceinline__ uint32_t swz(uint32_t b) { return b ^ ((b >> 3) & 0x70); }
__device__ __forceinline__ uint32_t bf2(float x, float y) {
    __nv_bfloat162 h = __floats2bfloat162_rn(x, y);
    return *(uint32_t*)&h;
}
__device__ __forceinline__ void ldsm4(uint32_t* r, uint32_t a) {
    asm volatile("ldmatrix.sync.aligned.m8n8.x4.shared.b16 {%0,%1,%2,%3}, [%4];"
        : "=r"(r[0]), "=r"(r[1]), "=r"(r[2]), "=r"(r[3]) : "r"(a));
}
__device__ __forceinline__ void mma16816(float* d, const uint32_t* a, const uint32_t* b) {
    asm volatile(
        "mma.sync.aligned.m16n8k16.row.col.f32.bf16.bf16.f32 "
        "{%0,%1,%2,%3}, {%4,%5,%6,%7}, {%8,%9}, {%0,%1,%2,%3};"
        : "+f"(d[0]), "+f"(d[1]), "+f"(d[2]), "+f"(d[3])
        : "r"(a[0]), "r"(a[1]), "r"(a[2]), "r"(a[3]), "r"(b[0]), "r"(b[1]));
}
__device__ __forceinline__ void cp16(uint32_t dst, const void* src) {
    asm volatile("cp.async.cg.shared.global [%0], [%1], 16;" :: "r"(dst), "l"(src) : "memory");
}

// ---------------- precompute tables ----------------
__global__ void spe_precompute(const float* __restrict__ freqs,
                               const float* __restrict__ offsets,
                               const float* __restrict__ gains) {
    int i = blockIdx.x * blockDim.x + threadIdx.x;
    const float scale = rsqrtf((float)(RR * DD));
    if (i < HH*DD*SS) {
        float f = freqs[i];
        float fr = 0.5f / (1.0f + expf(-f));
        g_tpfr[i] = 6.28318530717958647692f * fr;
        float o = offsets[i];
        float so, co;
        sincosf(o, &so, &co);
        g_co[i] = co;
        g_so[i] = so;
    }
    if (i < HH*DD*T2) {
        int hd = i / T2;
        int t  = i - hd * T2;
        float x = gains[hd*SS + (t % SS)];
        float sp = fmaxf(x, 0.0f) + log1pf(expf(-fabsf(x)));
        g_coef[i] = sp * scale;
    }
}

// ---------------- z transpose + coef-scale + bf16 hi/lo split ----------------
// z[b][h][d][t][r] (fp32) -> zT{hi,lo}[b][h][r][d*20+t] (bf16)
__global__ void spe_transpose(const float* __restrict__ zg) {
    int d = blockIdx.x, h = blockIdx.y, b = blockIdx.z;
    __shared__ float sm[T2][RR + 1];
    const float* zd = zg + (((size_t)(b*HH + h)*DD + d)*T2)*RR;
    const float* cf = g_coef + (h*DD + d)*T2;
    for (int i = threadIdx.x; i < T2*RR; i += 256) {
        int t = i >> 7, r = i & 127;
        sm[t][r] = zd[i] * cf[t];
    }
    __syncthreads();
    int r  = threadIdx.x >> 1;
    int t0 = (threadIdx.x & 1) * 10;
    size_t ob = ((size_t)(b*HH + h)*RR + r)*KTOT + d*T2 + t0;
    #pragma unroll
    for (int i = 0; i < 10; ++i) {
        float v = sm[t0 + i][r];
        __nv_bfloat16 hi = __float2bfloat16(v);
        __nv_bfloat16 lo = __float2bfloat16(v - __bfloat162float(hi));
        g_zThi[ob + i] = hi;
        g_zTlo[ob + i] = lo;
    }
}

// ---------------- main HMMA kernel ----------------
__global__ __launch_bounds__(256, 2)
void spe_mma_main(const float* __restrict__ qg,
                  const float* __restrict__ kg,
                  float* __restrict__ out) {
    extern __shared__ char smraw[];
    const uint32_t sb   = smem_u32(smraw);
    const uint32_t tb_u = (sb + 1023) & ~1023u;
    char* tb = smraw + (tb_u - sb);

    const int tid  = threadIdx.x;
    const int wid  = tid >> 5;
    const int lane = tid & 31;
    const int l0   = blockIdx.x * MT;
    const int h    = blockIdx.y;
    const int b    = blockIdx.z;

    const int mi = wid & 1;   // 2 m32 blocks
    const int ni = wid >> 1;  // 4 n32 blocks

    const __nv_bfloat16* zThi = g_zThi + (size_t)(b*HH + h)*RR*KTOT;
    const __nv_bfloat16* zTlo = g_zTlo + (size_t)(b*HH + h)*RR*KTOT;

    // stage chunk ch into the (single) buffer
    auto stage = [&](int ch) {
        const int k0 = ch * KC;
        // B: zT hi/lo via cp.async (overlaps with the A compute below)
        #pragma unroll
        for (int u = 0; u < 4; ++u) {
            int idx = tid + u*256;         // 1024 units of 8 bf16
            int r   = idx >> 3;
            int kl8 = (idx & 7) * 8;
            uint32_t byte = swz((uint32_t)(r*128 + kl8*2));
            cp16(tb_u + OFF_BH + byte, zThi + (size_t)r*KTOT + k0 + kl8);
            cp16(tb_u + OFF_BL + byte, zTlo + (size_t)r*KTOT + k0 + kl8);
        }
        asm volatile("cp.async.commit_group;" ::: "memory");
        // A: omega*q/k, bf16 hi/lo, [64 l][64 k]
        #pragma unroll
        for (int u = 0; u < 8; ++u) {
            int unit = tid + u*256;        // 2048 units: (l, k-pair)
            int l  = unit >> 5;
            int pi = unit & 31;
            int k  = k0 + 2*pi;
            int d  = k / T2;
            int s  = (k - d*T2) >> 1;
            int gb = (h*DD + d)*SS + s;
            float ph = g_tpfr[gb] * (float)(l0 + l);
            float sp, cp;
            sincosf(ph, &sp, &cp);
            float co = g_co[gb], so = g_so[gb];
            float cq = cp*co - sp*so;
            float sq = sp*co + cp*so;
            size_t gi = (((size_t)b*LL + (l0 + l))*HH + h)*DD + d;
            float qv = __ldg(qg + gi);
            float kv = __ldg(kg + gi);
            float aqc = cq*qv, aqs = sq*qv, akc = cp*kv, aks = sp*kv;

            uint32_t byte = swz((uint32_t)(l*128 + pi*4));
            uint32_t qh = bf2(aqc, aqs);
            uint32_t kh = bf2(akc, aks);
            __nv_bfloat162 qh2 = *(__nv_bfloat162*)&qh;
            __nv_bfloat162 kh2 = *(__nv_bfloat162*)&kh;
            uint32_t ql = bf2(aqc - __bfloat162float(qh2.x), aqs - __bfloat162float(qh2.y));
            uint32_t kl = bf2(akc - __bfloat162float(kh2.x), aks - __bfloat162float(kh2.y));
            *(uint32_t*)(tb + 0*TSZA + byte) = qh;
            *(uint32_t*)(tb + 1*TSZA + byte) = ql;
            *(uint32_t*)(tb + 2*TSZA + byte) = kh;
            *(uint32_t*)(tb + 3*TSZA + byte) = kl;
        }
    };

    // accumulators: [msub 2][ntile 4][4] for q and k
    float accq[2][4][4];
    float acck[2][4][4];
    #pragma unroll
    for (int i = 0; i < 2; ++i)
        #pragma unroll
        for (int j = 0; j < 4; ++j)
            #pragma unroll
            for (int c = 0; c < 4; ++c) { accq[i][j][c] = 0.0f; acck[i][j][c] = 0.0f; }

    const uint32_t lanerow = lane & 15;
    const uint32_t lanecol = (uint32_t)(lane >> 4) * 16;

    #pragma unroll 1
    for (int ch = 0; ch < NCH; ++ch) {
        stage(ch);
        asm volatile("cp.async.wait_group 0;" ::: "memory");
        __syncthreads();

        const uint32_t base = tb_u;
        #pragma unroll
        for (int kk = 0; kk < 4; ++kk) {
            const uint32_t kb = kk * 32;   // 16 elems * 2B
            // --- B fragments (shared by q and k) ---
            uint32_t bh[4][2], bl[4][2];
            {
                uint32_t t0[4], t1[4];
                uint32_t o0 = swz((ni*32 +  0 + lanerow)*128 + lanecol + kb);
                uint32_t o1 = swz((ni*32 + 16 + lanerow)*128 + lanecol + kb);
                ldsm4(t0, base + OFF_BH + o0);
                ldsm4(t1, base + OFF_BH + o1);
                bh[0][0]=t0[0]; bh[0][1]=t0[2]; bh[1][0]=t0[1]; bh[1][1]=t0[3];
                bh[2][0]=t1[0]; bh[2][1]=t1[2]; bh[3][0]=t1[1]; bh[3][1]=t1[3];
                ldsm4(t0, base + OFF_BL + o0);
                ldsm4(t1, base + OFF_BL + o1);
                bl[0][0]=t0[0]; bl[0][1]=t0[2]; bl[1][0]=t0[1]; bl[1][1]=t0[3];
                bl[2][0]=t1[0]; bl[2][1]=t1[2]; bl[3][0]=t1[1]; bl[3][1]=t1[3];
            }
            const uint32_t a0 = swz((mi*32 +  0 + lanerow)*128 + lanecol + kb);
            const uint32_t a1 = swz((mi*32 + 16 + lanerow)*128 + lanecol + kb);
            // --- q ---
            {
                uint32_t ah[2][4], al[2][4];
                ldsm4(ah[0], base + 0*TSZA + a0);
                ldsm4(ah[1], base + 0*TSZA + a1);
                ldsm4(al[0], base + 1*TSZA + a0);
                ldsm4(al[1], base + 1*TSZA + a1);
                #pragma unroll
                for (int s = 0; s < 2; ++s)
                    #pragma unroll
                    for (int j = 0; j < 4; ++j) {
                        mma16816(accq[s][j], ah[s], bh[j]);
                        mma16816(accq[s][j], al[s], bh[j]);
                        mma16816(accq[s][j], ah[s], bl[j]);
                    }
            }
            // --- k ---
            {
                uint32_t ah[2][4], al[2][4];
                ldsm4(ah[0], base + 2*TSZA + a0);
                ldsm4(ah[1], base + 2*TSZA + a1);
                ldsm4(al[0], base + 3*TSZA + a0);
                ldsm4(al[1], base + 3*TSZA + a1);
                #pragma unroll
                for (int s = 0; s < 2; ++s)
                    #pragma unroll
                    for (int j = 0; j < 4; ++j) {
                        mma16816(acck[s][j], ah[s], bh[j]);
                        mma16816(acck[s][j], al[s], bh[j]);
                        mma16816(acck[s][j], ah[s], bl[j]);
                    }
            }
        }
        __syncthreads();
    }

    // ---- epilogue: c-frag scatter ----
    const size_t khat_off = (size_t)BB * LL * HH * RR;
    #pragma unroll
    for (int s = 0; s < 2; ++s) {
        int row0 = l0 + mi*32 + s*16 + (lane >> 2);
        #pragma unroll
        for (int j = 0; j < 4; ++j) {
            int col = ni*32 + j*8 + (lane & 3)*2;
            size_t oA = (((size_t)b*LL + row0)*HH + h)*RR + col;
            size_t oB = oA + (size_t)8*HH*RR;   // row0 + 8
            *(float2*)(out + oA) = make_float2(accq[s][j][0], accq[s][j][1]);
            *(float2*)(out + oB) = make_float2(accq[s][j][2], accq[s][j][3]);
            *(float2*)(out + khat_off + oA) = make_float2(acck[s][j][0], acck[s][j][1]);
            *(float2*)(out + khat_off + oB) = make_float2(acck[s][j][2], acck[s][j][3]);
        }
    }
}

extern "C" void kernel_launch(void* const* d_in, const int* in_sizes, int n_in,
                              void* d_out, int out_size) {
    const float* queries = (const float*)d_in[0];
    const float* keys    = (const float*)d_in[1];
    const float* freqs   = (const float*)d_in[2];
    const float* offsets = (const float*)d_in[3];
    const float* gains   = (const float*)d_in[4];
    const float* z       = (const float*)d_in[5];
    float* out = (float*)d_out;

    cudaFuncSetAttribute(spe_mma_main, cudaFuncAttributeMaxDynamicSharedMemorySize, SMEM_BYTES);

    spe_precompute<<<(HH*DD*T2 + 255)/256, 256>>>(freqs, offsets, gains);
    spe_transpose<<<dim3(DD, HH, BB), 256>>>(z);
    spe_mma_main<<<dim3(LL/MT, HH, BB), 256, SMEM_BYTES>>>(queries, keys, out);
}